// round 1
// baseline (speedup 1.0000x reference)
#include <cuda_runtime.h>
#include <math.h>

#define HW    196
#define NB    32
#define NP    (NB * HW)      // 6272
#define CIN   512
#define DG    2048
#define HID   256
#define NEG_CNT (NP - HW)    // 6076
#define EPSV  1e-10f

// ---------------- scratch (no allocation allowed) ----------------
__device__ float g_hloc[NP * HID];     // 6.4 MB
__device__ float g_hglb[NB * HID];     // 32 KB
__device__ float g_scores[NB * NP];    // 800 KB

// ---------------- kernel 2: h_glb = gf @ W1[:D] + b1 ----------------
__global__ void k_hglb(const float* __restrict__ gf,
                       const float* __restrict__ W1,
                       const float* __restrict__ b1) {
    __shared__ float gs[DG];
    const int n = blockIdx.x;
    for (int i = threadIdx.x; i < DG; i += blockDim.x) gs[i] = gf[n * DG + i];
    __syncthreads();
    const int j = threadIdx.x;               // 256 threads = 256 outputs
    float acc = b1[j];
    #pragma unroll 8
    for (int k = 0; k < DG; k++) acc = fmaf(gs[k], W1[k * HID + j], acc);
    g_hglb[n * HID + j] = acc;
}

// ---------------- kernel 1: h_loc = lf(transposed) @ W1[D:] ----------------
// M=6272 (pixels), K=512, N=256.  64-pixel tile per block, 8x8 micro-tile.
__global__ __launch_bounds__(256) void k_hloc(const float* __restrict__ lf,
                                              const float* __restrict__ W1) {
    __shared__ float As[64][33];        // [pixel][k]  (+1 pad: conflict-free)
    __shared__ float Bs[32][HID];       // [k][j]
    const int tid = threadIdx.x;
    const int tx = tid & 31, ty = tid >> 5;
    const int p0 = blockIdx.x * 64;
    float acc[8][8] = {};

    for (int kc = 0; kc < CIN; kc += 32) {
        // As: lanes vary along pixel dim (contiguous in lf) -> coalesced
        #pragma unroll
        for (int i = 0; i < 8; i++) {
            int idx = tid + i * 256;
            int pp = idx & 63, k = idx >> 6;
            int p = p0 + pp;
            int n = p / HW, r = p - n * HW;
            As[pp][k] = lf[(n * CIN + kc + k) * HW + r];
        }
        // Bs: lanes vary along j (contiguous in W1) -> coalesced
        #pragma unroll
        for (int i = 0; i < 32; i++) {
            int idx = tid + i * 256;
            int j = idx & 255, k = idx >> 8;
            Bs[k][j] = W1[(DG + kc + k) * HID + j];
        }
        __syncthreads();
        #pragma unroll
        for (int k = 0; k < 32; k++) {
            float a[8], b[8];
            #pragma unroll
            for (int i = 0; i < 8; i++) a[i] = As[ty * 8 + i][k];
            float4 v0 = *(const float4*)&Bs[k][tx * 8];
            float4 v1 = *(const float4*)&Bs[k][tx * 8 + 4];
            b[0]=v0.x; b[1]=v0.y; b[2]=v0.z; b[3]=v0.w;
            b[4]=v1.x; b[5]=v1.y; b[6]=v1.z; b[7]=v1.w;
            #pragma unroll
            for (int i = 0; i < 8; i++)
                #pragma unroll
                for (int j = 0; j < 8; j++) acc[i][j] = fmaf(a[i], b[j], acc[i][j]);
        }
        __syncthreads();
    }
    #pragma unroll
    for (int i = 0; i < 8; i++) {
        int p = p0 + ty * 8 + i;
        #pragma unroll
        for (int j = 0; j < 8; j += 4) {
            float4 v = make_float4(acc[i][j], acc[i][j+1], acc[i][j+2], acc[i][j+3]);
            *(float4*)&g_hloc[p * HID + tx * 8 + j] = v;
        }
    }
}

// ---------------- kernel 3: fused h1 -> h2 -> scores ----------------
// grid (98 pixel tiles, 32 n).  h1 = relu(hglb[n] + hloc[p]) built in smem,
// GEMM vs W2 (K=256), epilogue applies relu+b2, contracts with W3 -> score.
__global__ __launch_bounds__(256) void k_main(const float* __restrict__ W2,
                                              const float* __restrict__ b2,
                                              const float* __restrict__ W3,
                                              const float* __restrict__ b3) {
    __shared__ float As[64][33];
    __shared__ float Bs[32][HID];
    __shared__ float gl[HID];
    const int tid = threadIdx.x;
    const int tx = tid & 31, ty = tid >> 5;
    const int p0 = blockIdx.x * 64;
    const int n  = blockIdx.y;

    gl[tid] = g_hglb[n * HID + tid];
    __syncthreads();

    float acc[8][8] = {};
    for (int kc = 0; kc < HID; kc += 32) {
        // As: lanes vary along k (contiguous in hloc rows) -> coalesced
        #pragma unroll
        for (int i = 0; i < 8; i++) {
            int idx = tid + i * 256;
            int k = idx & 31, pp = idx >> 5;
            float v = g_hloc[(p0 + pp) * HID + kc + k] + gl[kc + k];
            As[pp][k] = fmaxf(v, 0.0f);
        }
        #pragma unroll
        for (int i = 0; i < 32; i++) {
            int idx = tid + i * 256;
            int j = idx & 255, k = idx >> 8;
            Bs[k][j] = W2[(kc + k) * HID + j];
        }
        __syncthreads();
        #pragma unroll
        for (int k = 0; k < 32; k++) {
            float a[8], b[8];
            #pragma unroll
            for (int i = 0; i < 8; i++) a[i] = As[ty * 8 + i][k];
            float4 v0 = *(const float4*)&Bs[k][tx * 8];
            float4 v1 = *(const float4*)&Bs[k][tx * 8 + 4];
            b[0]=v0.x; b[1]=v0.y; b[2]=v0.z; b[3]=v0.w;
            b[4]=v1.x; b[5]=v1.y; b[6]=v1.z; b[7]=v1.w;
            #pragma unroll
            for (int i = 0; i < 8; i++)
                #pragma unroll
                for (int j = 0; j < 8; j++) acc[i][j] = fmaf(a[i], b[j], acc[i][j]);
        }
        __syncthreads();
    }

    // epilogue: h2 = relu(acc + b2); score_p = sum_j h2 * W3[j]  (+ b3)
    float w3r[8], b2r[8];
    #pragma unroll
    for (int j = 0; j < 8; j++) { w3r[j] = W3[tx * 8 + j]; b2r[j] = b2[tx * 8 + j]; }
    const float b3v = b3[0];
    #pragma unroll
    for (int i = 0; i < 8; i++) {
        float s = 0.0f;
        #pragma unroll
        for (int j = 0; j < 8; j++)
            s = fmaf(fmaxf(acc[i][j] + b2r[j], 0.0f), w3r[j], s);
        #pragma unroll
        for (int o = 16; o > 0; o >>= 1) s += __shfl_xor_sync(0xffffffffu, s, o);
        if (tx == 0) g_scores[n * NP + p0 + ty * 8 + i] = s + b3v;
    }
}

// ---------------- kernel 4: softmax-style reduction -> mi ----------------
__global__ void k_reduce(float* __restrict__ out) {
    __shared__ float red[256];
    const int n = blockIdx.x;
    const int tid = threadIdx.x;
    const float* s = &g_scores[n * NP];

    // pass A: global max (own included, matching reference)
    float mx = -INFINITY;
    for (int p = tid; p < NP; p += 256) mx = fmaxf(mx, s[p]);
    red[tid] = mx; __syncthreads();
    for (int o = 128; o > 0; o >>= 1) {
        if (tid < o) red[tid] = fmaxf(red[tid], red[tid + o]);
        __syncthreads();
    }
    mx = red[0]; __syncthreads();

    // pass B: sum of exp over non-own columns
    const int lo = n * HW, hi = lo + HW;
    float sum = 0.0f;
    for (int p = tid; p < NP; p += 256)
        if (p < lo || p >= hi) sum += expf(s[p] - mx);
    red[tid] = sum; __syncthreads();
    for (int o = 128; o > 0; o >>= 1) {
        if (tid < o) red[tid] += red[tid + o];
        __syncthreads();
    }
    const float neg_mean = red[0] / (float)NEG_CNT + EPSV;
    const float lm = logf(neg_mean);

    // pass C: mi for own pixels
    for (int r = tid; r < HW; r += 256)
        out[n * HW + r] = s[lo + r] - mx - lm;
}

// ---------------- launch ----------------
extern "C" void kernel_launch(void* const* d_in, const int* in_sizes, int n_in,
                              void* d_out, int out_size) {
    const float* lf = (const float*)d_in[0];   // local_feature (32,512,14,14)
    const float* gf = (const float*)d_in[1];   // global_feature (32,2048,1,1)
    const float* W1 = (const float*)d_in[2];   // (2560,256)
    const float* b1 = (const float*)d_in[3];   // (256,)
    const float* W2 = (const float*)d_in[4];   // (256,256)
    const float* b2 = (const float*)d_in[5];   // (256,)
    const float* W3 = (const float*)d_in[6];   // (256,1)
    const float* b3 = (const float*)d_in[7];   // (1,)
    float* out = (float*)d_out;                // (32,14,14) float32

    k_hglb<<<NB, HID>>>(gf, W1, b1);
    k_hloc<<<NP / 64, 256>>>(lf, W1);
    dim3 g3(NP / 64, NB);
    k_main<<<g3, 256>>>(W2, b2, W3, b3);
    k_reduce<<<NB, 256>>>(out);
}

// round 7
// speedup vs baseline: 2.4694x; 2.4694x over previous
#include <cuda_runtime.h>
#include <math.h>
#include <stdint.h>

#define HW    196
#define NB    32
#define NP    (NB * HW)      // 6272
#define CIN   512
#define DG    2048
#define HID   256
#define NEG_CNT (NP - HW)    // 6076
#define EPSV  1e-10f

// ---------------- scratch ----------------
__device__ float g_hloc[NP * HID];     // 6.4 MB
__device__ float g_hglb[NB * HID];     // 32 KB
__device__ float g_w2r[HID * HID];     // 256 KB (W2 rounded to tf32, [k][j])
__device__ float g_scores[NB * NP];    // 800 KB

// ---------------- helpers ----------------
__device__ __forceinline__ float to_tf32(float x) {
    float r; asm("cvt.rna.tf32.f32 %0, %1;" : "=f"(r) : "f"(x)); return r;
}
__device__ __forceinline__ uint32_t smem_u32(const void* p) {
    uint32_t a;
    asm("{ .reg .u64 t; cvta.to.shared.u64 t, %1; cvt.u32.u64 %0, t; }" : "=r"(a) : "l"(p));
    return a;
}
__device__ __forceinline__ void cp16(uint32_t sa, const void* ga) {
    asm volatile("cp.async.cg.shared.global [%0], [%1], 16;" :: "r"(sa), "l"(ga) : "memory");
}
#define CP_COMMIT() asm volatile("cp.async.commit_group;" ::: "memory")
#define CP_WAIT0()  asm volatile("cp.async.wait_group 0;" ::: "memory")

__device__ __forceinline__ void mma8(float& c0, float& c1, float& c2, float& c3,
                                     uint32_t a0, uint32_t a1, uint32_t a2, uint32_t a3,
                                     uint32_t b0, uint32_t b1) {
    asm volatile("mma.sync.aligned.m16n8k8.row.col.f32.tf32.tf32.f32 "
                 "{%0,%1,%2,%3}, {%4,%5,%6,%7}, {%8,%9}, {%0,%1,%2,%3};"
                 : "+f"(c0), "+f"(c1), "+f"(c2), "+f"(c3)
                 : "r"(a0), "r"(a1), "r"(a2), "r"(a3), "r"(b0), "r"(b1));
}

// ---------------- prep: W2 rounded to tf32 ----------------
__global__ void k_w2r(const float* __restrict__ W2) {
    int i = blockIdx.x * 256 + threadIdx.x;
    g_w2r[i] = to_tf32(W2[i]);
}

// ---------------- h_glb = gf @ W1[:D] + b1 ----------------
__global__ void k_hglb(const float* __restrict__ gf,
                       const float* __restrict__ W1,
                       const float* __restrict__ b1) {
    __shared__ float gs[DG];
    const int n = blockIdx.x;
    for (int i = threadIdx.x; i < DG; i += blockDim.x) gs[i] = gf[n * DG + i];
    __syncthreads();
    const int j = threadIdx.x;
    float acc = b1[j];
    #pragma unroll 8
    for (int k = 0; k < DG; k++) acc = fmaf(gs[k], W1[k * HID + j], acc);
    g_hglb[n * HID + j] = acc;
}

// ---------------- h_loc = lf(transposed) @ W1[D:]  (fp32, exact) ----------------
__global__ __launch_bounds__(256) void k_hloc(const float* __restrict__ lf,
                                              const float* __restrict__ W1) {
    __shared__ float As[64][33];
    __shared__ float Bs[32][HID];
    const int tid = threadIdx.x;
    const int tx = tid & 31, ty = tid >> 5;
    const int p0 = blockIdx.x * 64;
    float acc[8][8] = {};

    for (int kc = 0; kc < CIN; kc += 32) {
        #pragma unroll
        for (int i = 0; i < 8; i++) {
            int idx = tid + i * 256;
            int pp = idx & 63, k = idx >> 6;
            int p = p0 + pp;
            int n = p / HW, r = p - n * HW;
            As[pp][k] = lf[(n * CIN + kc + k) * HW + r];
        }
        #pragma unroll
        for (int i = 0; i < 32; i++) {
            int idx = tid + i * 256;
            int j = idx & 255, k = idx >> 8;
            Bs[k][j] = W1[(DG + kc + k) * HID + j];
        }
        __syncthreads();
        #pragma unroll
        for (int k = 0; k < 32; k++) {
            float a[8], b[8];
            #pragma unroll
            for (int i = 0; i < 8; i++) a[i] = As[ty * 8 + i][k];
            float4 v0 = *(const float4*)&Bs[k][tx * 8];
            float4 v1 = *(const float4*)&Bs[k][tx * 8 + 4];
            b[0]=v0.x; b[1]=v0.y; b[2]=v0.z; b[3]=v0.w;
            b[4]=v1.x; b[5]=v1.y; b[6]=v1.z; b[7]=v1.w;
            #pragma unroll
            for (int i = 0; i < 8; i++)
                #pragma unroll
                for (int j = 0; j < 8; j++) acc[i][j] = fmaf(a[i], b[j], acc[i][j]);
        }
        __syncthreads();
    }
    #pragma unroll
    for (int i = 0; i < 8; i++) {
        int p = p0 + ty * 8 + i;
        #pragma unroll
        for (int j = 0; j < 8; j += 4) {
            float4 v = make_float4(acc[i][j], acc[i][j+1], acc[i][j+2], acc[i][j+3]);
            *(float4*)&g_hloc[p * HID + tx * 8 + j] = v;
        }
    }
}

// ---------------- main fused kernel: warp-level tf32 MMA ----------------
// grid (49, 32). CTA: 512 thr (16 warps, 4x4). Tile M=128 x N=256 x K=256.
// smem (floats): gl[256] | b2[256] | w3[256] | sc[512] | A 2x128x36 | B 2x32x264
#define SMF_GL  0
#define SMF_B2  256
#define SMF_W3  512
#define SMF_SC  768
#define SMF_A   1280
#define SMF_B   10496
#define SMF_TOT 27392            // floats -> 109568 bytes
#define A_STRIDE 36
#define B_STRIDE 264

__global__ __launch_bounds__(512, 1) void k_main_mma(const float* __restrict__ b2,
                                                     const float* __restrict__ W3,
                                                     const float* __restrict__ b3) {
    extern __shared__ float sm[];
    float* gls = sm + SMF_GL;
    float* b2s = sm + SMF_B2;
    float* w3s = sm + SMF_W3;
    float* sc  = sm + SMF_SC;

    const int tid = threadIdx.x;
    const int wid = tid >> 5, lane = tid & 31;
    const int wm = wid & 3, wn = wid >> 2;
    const int g = lane >> 2, tig = lane & 3;
    const int p0 = blockIdx.x * 128;
    const int n  = blockIdx.y;

    for (int i = tid; i < HID; i += 512) {
        gls[i] = g_hglb[n * HID + i];
        b2s[i] = b2[i];
        w3s[i] = W3[i];
    }
    __syncthreads();

    const float4* hl4 = (const float4*)g_hloc;
    const float4* gl4 = (const float4*)gls;

    float acc[2][8][4];
    #pragma unroll
    for (int mi = 0; mi < 2; mi++)
        #pragma unroll
        for (int f = 0; f < 8; f++)
            #pragma unroll
            for (int q = 0; q < 4; q++) acc[mi][f][q] = 0.0f;

    float4 aF[2];

    // ---- prologue: chunk 0 ----
    {
        #pragma unroll
        for (int i = 0; i < 2; i++) {
            int id = tid + i * 512;
            int row = id >> 3, kq = id & 7;
            float4 v = hl4[(size_t)(p0 + row) * 64 + kq];
            float4 gg = gl4[kq];
            v.x = to_tf32(fmaxf(v.x + gg.x, 0.0f));
            v.y = to_tf32(fmaxf(v.y + gg.y, 0.0f));
            v.z = to_tf32(fmaxf(v.z + gg.z, 0.0f));
            v.w = to_tf32(fmaxf(v.w + gg.w, 0.0f));
            aF[i] = v;
        }
        uint32_t bB = smem_u32(sm + SMF_B);
        #pragma unroll
        for (int i = 0; i < 4; i++) {
            int id = tid + i * 512;
            int kr = id >> 6, jq = id & 63;
            cp16(bB + (uint32_t)(kr * (B_STRIDE * 4) + jq * 16),
                 g_w2r + (size_t)kr * HID + jq * 4);
        }
        CP_COMMIT();
        float* As = sm + SMF_A;
        #pragma unroll
        for (int i = 0; i < 2; i++) {
            int id = tid + i * 512;
            int row = id >> 3, kq = id & 7;
            *(float4*)(As + row * A_STRIDE + kq * 4) = aF[i];
        }
        CP_WAIT0();
        __syncthreads();
    }

    // ---- main loop over 8 K-chunks ----
    for (int c = 0; c < 8; c++) {
        float* As = sm + SMF_A + (c & 1) * (128 * A_STRIDE);
        float* Bs = sm + SMF_B + (c & 1) * (32 * B_STRIDE);

        if (c < 7) {
            #pragma unroll
            for (int i = 0; i < 2; i++) {
                int id = tid + i * 512;
                int row = id >> 3, kq = id & 7;
                float4 v = hl4[(size_t)(p0 + row) * 64 + (c + 1) * 8 + kq];
                float4 gg = gl4[(c + 1) * 8 + kq];
                v.x = to_tf32(fmaxf(v.x + gg.x, 0.0f));
                v.y = to_tf32(fmaxf(v.y + gg.y, 0.0f));
                v.z = to_tf32(fmaxf(v.z + gg.z, 0.0f));
                v.w = to_tf32(fmaxf(v.w + gg.w, 0.0f));
                aF[i] = v;
            }
            uint32_t bB = smem_u32(sm + SMF_B + ((c + 1) & 1) * (32 * B_STRIDE));
            #pragma unroll
            for (int i = 0; i < 4; i++) {
                int id = tid + i * 512;
                int kr = id >> 6, jq = id & 63;
                cp16(bB + (uint32_t)(kr * (B_STRIDE * 4) + jq * 16),
                     g_w2r + (size_t)((c + 1) * 32 + kr) * HID + jq * 4);
            }
            CP_COMMIT();
        }

        const float* Aw = As + (wm * 32) * A_STRIDE;
        const float* Bw = Bs + wn * 64;
        #pragma unroll
        for (int s = 0; s < 4; s++) {
            const int kb = s * 8;
            uint32_t a[2][4];
            #pragma unroll
            for (int mi = 0; mi < 2; mi++) {
                const float* ap = Aw + (mi * 16 + g) * A_STRIDE + kb + tig;
                a[mi][0] = __float_as_uint(ap[0]);
                a[mi][1] = __float_as_uint(ap[8 * A_STRIDE]);
                a[mi][2] = __float_as_uint(ap[4]);
                a[mi][3] = __float_as_uint(ap[8 * A_STRIDE + 4]);
            }
            #pragma unroll
            for (int f = 0; f < 8; f++) {
                const float* bp = Bw + (kb + tig) * B_STRIDE + f * 8 + g;
                uint32_t b0 = __float_as_uint(bp[0]);
                uint32_t b1 = __float_as_uint(bp[4 * B_STRIDE]);
                mma8(acc[0][f][0], acc[0][f][1], acc[0][f][2], acc[0][f][3],
                     a[0][0], a[0][1], a[0][2], a[0][3], b0, b1);
                mma8(acc[1][f][0], acc[1][f][1], acc[1][f][2], acc[1][f][3],
                     a[1][0], a[1][1], a[1][2], a[1][3], b0, b1);
            }
        }

        if (c < 7) {
            float* An = sm + SMF_A + ((c + 1) & 1) * (128 * A_STRIDE);
            #pragma unroll
            for (int i = 0; i < 2; i++) {
                int id = tid + i * 512;
                int row = id >> 3, kq = id & 7;
                *(float4*)(An + row * A_STRIDE + kq * 4) = aF[i];
            }
            CP_WAIT0();
        }
        __syncthreads();
    }

    // ---- epilogue: score = sum_j relu(acc + b2[j]) * W3[j] ----
    float pr[2][2] = {};
    #pragma unroll
    for (int mi = 0; mi < 2; mi++)
        #pragma unroll
        for (int f = 0; f < 8; f++) {
            const int c0col = wn * 64 + f * 8 + tig * 2;
            const int c1col = c0col + 1;
            pr[mi][0] += fmaxf(acc[mi][f][0] + b2s[c0col], 0.0f) * w3s[c0col]
                       + fmaxf(acc[mi][f][1] + b2s[c1col], 0.0f) * w3s[c1col];
            pr[mi][1] += fmaxf(acc[mi][f][2] + b2s[c0col], 0.0f) * w3s[c0col]
                       + fmaxf(acc[mi][f][3] + b2s[c1col], 0.0f) * w3s[c1col];
        }
    #pragma unroll
    for (int mi = 0; mi < 2; mi++)
        #pragma unroll
        for (int h = 0; h < 2; h++) {
            float v = pr[mi][h];
            v += __shfl_xor_sync(0xffffffffu, v, 1);
            v += __shfl_xor_sync(0xffffffffu, v, 2);
            if (tig == 0) sc[wn * 128 + wm * 32 + mi * 16 + h * 8 + g] = v;
        }
    __syncthreads();
    if (tid < 128) {
        float s = sc[tid] + sc[128 + tid] + sc[256 + tid] + sc[384 + tid] + b3[0];
        g_scores[n * NP + p0 + tid] = s;
    }
}

// ---------------- reduction ----------------
__global__ void k_reduce(float* __restrict__ out) {
    __shared__ float red[256];
    const int n = blockIdx.x;
    const int tid = threadIdx.x;
    const float* s = &g_scores[n * NP];

    float mx = -INFINITY;
    for (int p = tid; p < NP; p += 256) mx = fmaxf(mx, s[p]);
    red[tid] = mx; __syncthreads();
    for (int o = 128; o > 0; o >>= 1) {
        if (tid < o) red[tid] = fmaxf(red[tid], red[tid + o]);
        __syncthreads();
    }
    mx = red[0]; __syncthreads();

    const int lo = n * HW, hi = lo + HW;
    float sum = 0.0f;
    for (int p = tid; p < NP; p += 256)
        if (p < lo || p >= hi) sum += expf(s[p] - mx);
    red[tid] = sum; __syncthreads();
    for (int o = 128; o > 0; o >>= 1) {
        if (tid < o) red[tid] += red[tid + o];
        __syncthreads();
    }
    const float neg_mean = red[0] / (float)NEG_CNT + EPSV;
    const float lm = logf(neg_mean);

    for (int r = tid; r < HW; r += 256)
        out[n * HW + r] = s[lo + r] - mx - lm;
}

// ---------------- launch ----------------
extern "C" void kernel_launch(void* const* d_in, const int* in_sizes, int n_in,
                              void* d_out, int out_size) {
    const float* lf = (const float*)d_in[0];
    const float* gf = (const float*)d_in[1];
    const float* W1 = (const float*)d_in[2];
    const float* b1 = (const float*)d_in[3];
    const float* W2 = (const float*)d_in[4];
    const float* b2 = (const float*)d_in[5];
    const float* W3 = (const float*)d_in[6];
    const float* b3 = (const float*)d_in[7];
    float* out = (float*)d_out;

    cudaFuncSetAttribute(k_main_mma, cudaFuncAttributeMaxDynamicSharedMemorySize,
                         SMF_TOT * 4);

    k_w2r<<<HID * HID / 256, 256>>>(W2);
    k_hglb<<<NB, HID>>>(gf, W1, b1);
    k_hloc<<<NP / 64, 256>>>(lf, W1);
    { dim3 g3(NP / 128, NB); k_main_mma<<<g3, 512, SMF_TOT * 4>>>(b2, W3, b3); }
    k_reduce<<<NB, 256>>>(out);
}

// round 9
// speedup vs baseline: 2.5461x; 1.0311x over previous
#include <cuda_runtime.h>
#include <math.h>
#include <stdint.h>

#define HW    196
#define NB    32
#define NP    (NB * HW)      // 6272
#define CIN   512
#define DG    2048
#define HID   256
#define NEG_CNT (NP - HW)    // 6076
#define EPSV  1e-10f

// ---------------- scratch ----------------
__device__ float g_hloc[NP * HID];     // 6.4 MB
__device__ float g_hglb[NB * HID];     // 32 KB
__device__ float g_w2r[HID * HID];     // 256 KB (W2 tf32-rounded, [k][j])
__device__ float g_w1h[CIN * HID];     // 512 KB (W1[D:] tf32 hi, [k][j])
__device__ float g_w1l[CIN * HID];     // 512 KB (W1[D:] tf32 lo, [k][j])
__device__ float g_scores[NB * NP];    // 800 KB

// ---------------- helpers ----------------
__device__ __forceinline__ float to_tf32(float x) {
    float r; asm("cvt.rna.tf32.f32 %0, %1;" : "=f"(r) : "f"(x)); return r;
}
__device__ __forceinline__ uint32_t smem_u32(const void* p) {
    uint32_t a;
    asm("{ .reg .u64 t; cvta.to.shared.u64 t, %1; cvt.u32.u64 %0, t; }" : "=r"(a) : "l"(p));
    return a;
}
__device__ __forceinline__ void cp16(uint32_t sa, const void* ga) {
    asm volatile("cp.async.cg.shared.global [%0], [%1], 16;" :: "r"(sa), "l"(ga) : "memory");
}
#define CP_COMMIT() asm volatile("cp.async.commit_group;" ::: "memory")
#define CP_WAIT0()  asm volatile("cp.async.wait_group 0;" ::: "memory")

__device__ __forceinline__ void mma8(float& c0, float& c1, float& c2, float& c3,
                                     uint32_t a0, uint32_t a1, uint32_t a2, uint32_t a3,
                                     uint32_t b0, uint32_t b1) {
    asm volatile("mma.sync.aligned.m16n8k8.row.col.f32.tf32.tf32.f32 "
                 "{%0,%1,%2,%3}, {%4,%5,%6,%7}, {%8,%9}, {%0,%1,%2,%3};"
                 : "+f"(c0), "+f"(c1), "+f"(c2), "+f"(c3)
                 : "r"(a0), "r"(a1), "r"(a2), "r"(a3), "r"(b0), "r"(b1));
}

// ---------------- prep: W2 -> tf32 ----------------
__global__ void k_w2r(const float* __restrict__ W2) {
    int i = blockIdx.x * 256 + threadIdx.x;
    g_w2r[i] = to_tf32(W2[i]);
}

// ---------------- prep: W1[D:] -> tf32 hi/lo split ----------------
__global__ void k_w1split(const float* __restrict__ W1) {
    int i = blockIdx.x * 256 + threadIdx.x;   // i over CIN*HID
    float w = W1[(size_t)DG * HID + i];
    float h = to_tf32(w);
    g_w1h[i] = h;
    g_w1l[i] = to_tf32(w - h);
}

// ---------------- h_glb = gf @ W1[:D] + b1 ----------------
__global__ void k_hglb(const float* __restrict__ gf,
                       const float* __restrict__ W1,
                       const float* __restrict__ b1) {
    __shared__ float gs[DG];
    const int n = blockIdx.x;
    for (int i = threadIdx.x; i < DG; i += blockDim.x) gs[i] = gf[n * DG + i];
    __syncthreads();
    const int j = threadIdx.x;
    float acc = b1[j];
    #pragma unroll 8
    for (int k = 0; k < DG; k++) acc = fmaf(gs[k], W1[k * HID + j], acc);
    g_hglb[n * HID + j] = acc;
}

// ---------------- h_loc via split-tf32 MMA ----------------
// grid (49, 2): 128-pixel tile x 128-col half. 512 thr, 16 warps 4x4,
// warp tile 32x32. K=512 in 16 chunks of 32.
// smem floats: Ah[128*36] Al[128*36] Bh[32*136] Bl[32*136] = 17920 fl (71680 B)
#define HLA_STR 36
#define HLB_STR 136
#define HL_AH   0
#define HL_AL   4608
#define HL_BH   9216
#define HL_BL   13568
#define HL_TOT  17920

__global__ __launch_bounds__(512, 1) void k_hloc_mma(const float* __restrict__ lf) {
    extern __shared__ float sh[];
    float* Ah = sh + HL_AH;
    float* Al = sh + HL_AL;
    float* Bh = sh + HL_BH;
    float* Bl = sh + HL_BL;

    const int tid = threadIdx.x;
    const int wid = tid >> 5, lane = tid & 31;
    const int wm = wid & 3, wn = wid >> 2;
    const int g = lane >> 2, tig = lane & 3;
    const int p0 = blockIdx.x * 128;
    const int j0 = blockIdx.y * 128;

    float acc_h[2][4][4] = {};   // Ah*Bh
    float acc_x[2][4][4] = {};   // Ah*Bl + Al*Bh

    for (int c = 0; c < 16; c++) {
        const int kc = c * 32;
        // gather lf: 128 pixels x 32 k; lanes sweep pixel dim -> coalesced
        float va[8];
        #pragma unroll
        for (int i = 0; i < 8; i++) {
            int id = tid + i * 512;
            int pp = id & 127, k = id >> 7;
            int p = p0 + pp;
            int n = p / HW, r = p - n * HW;
            va[i] = lf[((size_t)n * CIN + kc + k) * HW + r];
        }
        __syncthreads();   // previous chunk's MMA reads done
        #pragma unroll
        for (int i = 0; i < 8; i++) {
            int id = tid + i * 512;
            int pp = id & 127, k = id >> 7;
            float h = to_tf32(va[i]);
            Ah[pp * HLA_STR + k] = h;
            Al[pp * HLA_STR + k] = to_tf32(va[i] - h);
        }
        // B: cp.async 32 rows x 128 cols for both hi and lo
        {
            uint32_t bh = smem_u32(Bh), bl = smem_u32(Bl);
            #pragma unroll
            for (int i = 0; i < 2; i++) {
                int idq = tid + i * 512;          // 0..1023
                int kr = idq >> 5, seg = idq & 31;
                uint32_t off = (uint32_t)(kr * HLB_STR + seg * 4) * 4;
                size_t src = (size_t)(kc + kr) * HID + j0 + seg * 4;
                cp16(bh + off, g_w1h + src);
                cp16(bl + off, g_w1l + src);
            }
        }
        CP_COMMIT();
        CP_WAIT0();
        __syncthreads();

        const float* Awh = Ah + (wm * 32) * HLA_STR;
        const float* Awl = Al + (wm * 32) * HLA_STR;
        #pragma unroll
        for (int s = 0; s < 4; s++) {
            const int kb = s * 8;
            uint32_t ah[2][4], al[2][4];
            #pragma unroll
            for (int mi = 0; mi < 2; mi++) {
                int ro = (mi * 16 + g) * HLA_STR + kb + tig;
                ah[mi][0] = __float_as_uint(Awh[ro]);
                ah[mi][1] = __float_as_uint(Awh[ro + 8 * HLA_STR]);
                ah[mi][2] = __float_as_uint(Awh[ro + 4]);
                ah[mi][3] = __float_as_uint(Awh[ro + 8 * HLA_STR + 4]);
                al[mi][0] = __float_as_uint(Awl[ro]);
                al[mi][1] = __float_as_uint(Awl[ro + 8 * HLA_STR]);
                al[mi][2] = __float_as_uint(Awl[ro + 4]);
                al[mi][3] = __float_as_uint(Awl[ro + 8 * HLA_STR + 4]);
            }
            #pragma unroll
            for (int f = 0; f < 4; f++) {
                const int col = wn * 32 + f * 8 + g;
                uint32_t bh0 = __float_as_uint(Bh[(kb + tig) * HLB_STR + col]);
                uint32_t bh1 = __float_as_uint(Bh[(kb + tig + 4) * HLB_STR + col]);
                uint32_t bl0 = __float_as_uint(Bl[(kb + tig) * HLB_STR + col]);
                uint32_t bl1 = __float_as_uint(Bl[(kb + tig + 4) * HLB_STR + col]);
                #pragma unroll
                for (int mi = 0; mi < 2; mi++) {
                    mma8(acc_h[mi][f][0], acc_h[mi][f][1], acc_h[mi][f][2], acc_h[mi][f][3],
                         ah[mi][0], ah[mi][1], ah[mi][2], ah[mi][3], bh0, bh1);
                    mma8(acc_x[mi][f][0], acc_x[mi][f][1], acc_x[mi][f][2], acc_x[mi][f][3],
                         ah[mi][0], ah[mi][1], ah[mi][2], ah[mi][3], bl0, bl1);
                    mma8(acc_x[mi][f][0], acc_x[mi][f][1], acc_x[mi][f][2], acc_x[mi][f][3],
                         al[mi][0], al[mi][1], al[mi][2], al[mi][3], bh0, bh1);
                }
            }
        }
    }

    // epilogue: h = acc_h + acc_x, fp32 stores
    #pragma unroll
    for (int mi = 0; mi < 2; mi++) {
        const int r0 = p0 + wm * 32 + mi * 16 + g;
        const int r1 = r0 + 8;
        #pragma unroll
        for (int f = 0; f < 4; f++) {
            const int col = j0 + wn * 32 + f * 8 + tig * 2;
            float2 v0 = make_float2(acc_h[mi][f][0] + acc_x[mi][f][0],
                                    acc_h[mi][f][1] + acc_x[mi][f][1]);
            float2 v1 = make_float2(acc_h[mi][f][2] + acc_x[mi][f][2],
                                    acc_h[mi][f][3] + acc_x[mi][f][3]);
            *(float2*)&g_hloc[(size_t)r0 * HID + col] = v0;
            *(float2*)&g_hloc[(size_t)r1 * HID + col] = v1;
        }
    }
}

// ---------------- main fused kernel: warp-level tf32 MMA ----------------
// grid (49, 32). CTA: 512 thr (16 warps, 4x4). Tile M=128 x N=256 x K=256.
#define SMF_GL  0
#define SMF_B2  256
#define SMF_W3  512
#define SMF_SC  768
#define SMF_A   1280
#define SMF_B   10496
#define SMF_TOT 27392            // floats -> 109568 bytes
#define A_STRIDE 36
#define B_STRIDE 264

__global__ __launch_bounds__(512, 1) void k_main_mma(const float* __restrict__ b2,
                                                     const float* __restrict__ W3,
                                                     const float* __restrict__ b3) {
    extern __shared__ float sm[];
    float* gls = sm + SMF_GL;
    float* b2s = sm + SMF_B2;
    float* w3s = sm + SMF_W3;
    float* sc  = sm + SMF_SC;

    const int tid = threadIdx.x;
    const int wid = tid >> 5, lane = tid & 31;
    const int wm = wid & 3, wn = wid >> 2;
    const int g = lane >> 2, tig = lane & 3;
    const int p0 = blockIdx.x * 128;
    const int n  = blockIdx.y;

    for (int i = tid; i < HID; i += 512) {
        gls[i] = g_hglb[n * HID + i];
        b2s[i] = b2[i];
        w3s[i] = W3[i];
    }
    __syncthreads();

    const float4* hl4 = (const float4*)g_hloc;
    const float4* gl4 = (const float4*)gls;

    float acc[2][8][4];
    #pragma unroll
    for (int mi = 0; mi < 2; mi++)
        #pragma unroll
        for (int f = 0; f < 8; f++)
            #pragma unroll
            for (int q = 0; q < 4; q++) acc[mi][f][q] = 0.0f;

    float4 aF[2];

    // ---- prologue: chunk 0 ----
    {
        #pragma unroll
        for (int i = 0; i < 2; i++) {
            int id = tid + i * 512;
            int row = id >> 3, kq = id & 7;
            float4 v = hl4[(size_t)(p0 + row) * 64 + kq];
            float4 gg = gl4[kq];
            v.x = to_tf32(fmaxf(v.x + gg.x, 0.0f));
            v.y = to_tf32(fmaxf(v.y + gg.y, 0.0f));
            v.z = to_tf32(fmaxf(v.z + gg.z, 0.0f));
            v.w = to_tf32(fmaxf(v.w + gg.w, 0.0f));
            aF[i] = v;
        }
        uint32_t bB = smem_u32(sm + SMF_B);
        #pragma unroll
        for (int i = 0; i < 4; i++) {
            int id = tid + i * 512;
            int kr = id >> 6, jq = id & 63;
            cp16(bB + (uint32_t)(kr * (B_STRIDE * 4) + jq * 16),
                 g_w2r + (size_t)kr * HID + jq * 4);
        }
        CP_COMMIT();
        float* As = sm + SMF_A;
        #pragma unroll
        for (int i = 0; i < 2; i++) {
            int id = tid + i * 512;
            int row = id >> 3, kq = id & 7;
            *(float4*)(As + row * A_STRIDE + kq * 4) = aF[i];
        }
        CP_WAIT0();
        __syncthreads();
    }

    // ---- main loop over 8 K-chunks ----
    for (int c = 0; c < 8; c++) {
        float* As = sm + SMF_A + (c & 1) * (128 * A_STRIDE);
        float* Bs = sm + SMF_B + (c & 1) * (32 * B_STRIDE);

        if (c < 7) {
            #pragma unroll
            for (int i = 0; i < 2; i++) {
                int id = tid + i * 512;
                int row = id >> 3, kq = id & 7;
                float4 v = hl4[(size_t)(p0 + row) * 64 + (c + 1) * 8 + kq];
                float4 gg = gl4[(c + 1) * 8 + kq];
                v.x = to_tf32(fmaxf(v.x + gg.x, 0.0f));
                v.y = to_tf32(fmaxf(v.y + gg.y, 0.0f));
                v.z = to_tf32(fmaxf(v.z + gg.z, 0.0f));
                v.w = to_tf32(fmaxf(v.w + gg.w, 0.0f));
                aF[i] = v;
            }
            uint32_t bB = smem_u32(sm + SMF_B + ((c + 1) & 1) * (32 * B_STRIDE));
            #pragma unroll
            for (int i = 0; i < 4; i++) {
                int id = tid + i * 512;
                int kr = id >> 6, jq = id & 63;
                cp16(bB + (uint32_t)(kr * (B_STRIDE * 4) + jq * 16),
                     g_w2r + (size_t)((c + 1) * 32 + kr) * HID + jq * 4);
            }
            CP_COMMIT();
        }

        const float* Aw = As + (wm * 32) * A_STRIDE;
        const float* Bw = Bs + wn * 64;
        #pragma unroll
        for (int s = 0; s < 4; s++) {
            const int kb = s * 8;
            uint32_t a[2][4];
            #pragma unroll
            for (int mi = 0; mi < 2; mi++) {
                const float* ap = Aw + (mi * 16 + g) * A_STRIDE + kb + tig;
                a[mi][0] = __float_as_uint(ap[0]);
                a[mi][1] = __float_as_uint(ap[8 * A_STRIDE]);
                a[mi][2] = __float_as_uint(ap[4]);
                a[mi][3] = __float_as_uint(ap[8 * A_STRIDE + 4]);
            }
            #pragma unroll
            for (int f = 0; f < 8; f++) {
                const float* bp = Bw + (kb + tig) * B_STRIDE + f * 8 + g;
                uint32_t b0 = __float_as_uint(bp[0]);
                uint32_t b1 = __float_as_uint(bp[4 * B_STRIDE]);
                mma8(acc[0][f][0], acc[0][f][1], acc[0][f][2], acc[0][f][3],
                     a[0][0], a[0][1], a[0][2], a[0][3], b0, b1);
                mma8(acc[1][f][0], acc[1][f][1], acc[1][f][2], acc[1][f][3],
                     a[1][0], a[1][1], a[1][2], a[1][3], b0, b1);
            }
        }

        if (c < 7) {
            float* An = sm + SMF_A + ((c + 1) & 1) * (128 * A_STRIDE);
            #pragma unroll
            for (int i = 0; i < 2; i++) {
                int id = tid + i * 512;
                int row = id >> 3, kq = id & 7;
                *(float4*)(An + row * A_STRIDE + kq * 4) = aF[i];
            }
            CP_WAIT0();
        }
        __syncthreads();
    }

    // ---- epilogue: score = sum_j relu(acc + b2[j]) * W3[j] ----
    float pr[2][2] = {};
    #pragma unroll
    for (int mi = 0; mi < 2; mi++)
        #pragma unroll
        for (int f = 0; f < 8; f++) {
            const int c0col = wn * 64 + f * 8 + tig * 2;
            const int c1col = c0col + 1;
            pr[mi][0] += fmaxf(acc[mi][f][0] + b2s[c0col], 0.0f) * w3s[c0col]
                       + fmaxf(acc[mi][f][1] + b2s[c1col], 0.0f) * w3s[c1col];
            pr[mi][1] += fmaxf(acc[mi][f][2] + b2s[c0col], 0.0f) * w3s[c0col]
                       + fmaxf(acc[mi][f][3] + b2s[c1col], 0.0f) * w3s[c1col];
        }
    #pragma unroll
    for (int mi = 0; mi < 2; mi++)
        #pragma unroll
        for (int h = 0; h < 2; h++) {
            float v = pr[mi][h];
            v += __shfl_xor_sync(0xffffffffu, v, 1);
            v += __shfl_xor_sync(0xffffffffu, v, 2);
            if (tig == 0) sc[wn * 128 + wm * 32 + mi * 16 + h * 8 + g] = v;
        }
    __syncthreads();
    if (tid < 128) {
        float s = sc[tid] + sc[128 + tid] + sc[256 + tid] + sc[384 + tid] + b3[0];
        g_scores[n * NP + p0 + tid] = s;
    }
}

// ---------------- reduction ----------------
__global__ void k_reduce(float* __restrict__ out) {
    __shared__ float red[256];
    const int n = blockIdx.x;
    const int tid = threadIdx.x;
    const float* s = &g_scores[n * NP];

    float mx = -INFINITY;
    for (int p = tid; p < NP; p += 256) mx = fmaxf(mx, s[p]);
    red[tid] = mx; __syncthreads();
    for (int o = 128; o > 0; o >>= 1) {
        if (tid < o) red[tid] = fmaxf(red[tid], red[tid + o]);
        __syncthreads();
    }
    mx = red[0]; __syncthreads();

    const int lo = n * HW, hi = lo + HW;
    float sum = 0.0f;
    for (int p = tid; p < NP; p += 256)
        if (p < lo || p >= hi) sum += expf(s[p] - mx);
    red[tid] = sum; __syncthreads();
    for (int o = 128; o > 0; o >>= 1) {
        if (tid < o) red[tid] += red[tid + o];
        __syncthreads();
    }
    const float neg_mean = red[0] / (float)NEG_CNT + EPSV;
    const float lm = logf(neg_mean);

    for (int r = tid; r < HW; r += 256)
        out[n * HW + r] = s[lo + r] - mx - lm;
}

// ---------------- launch ----------------
extern "C" void kernel_launch(void* const* d_in, const int* in_sizes, int n_in,
                              void* d_out, int out_size) {
    const float* lf = (const float*)d_in[0];
    const float* gf = (const float*)d_in[1];
    const float* W1 = (const float*)d_in[2];
    const float* b1 = (const float*)d_in[3];
    const float* W2 = (const float*)d_in[4];
    const float* b2 = (const float*)d_in[5];
    const float* W3 = (const float*)d_in[6];
    const float* b3 = (const float*)d_in[7];
    float* out = (float*)d_out;

    cudaFuncSetAttribute(k_main_mma, cudaFuncAttributeMaxDynamicSharedMemorySize,
                         SMF_TOT * 4);
    cudaFuncSetAttribute(k_hloc_mma, cudaFuncAttributeMaxDynamicSharedMemorySize,
                         HL_TOT * 4);

    k_w2r<<<HID * HID / 256, 256>>>(W2);
    k_w1split<<<CIN * HID / 256, 256>>>(W1);
    k_hglb<<<NB, HID>>>(gf, W1, b1);
    { dim3 gh(NP / 128, 2); k_hloc_mma<<<gh, 512, HL_TOT * 4>>>(lf); }
    { dim3 g3(NP / 128, NB); k_main_mma<<<g3, 512, SMF_TOT * 4>>>(b2, W3, b3); }
    k_reduce<<<NB, 256>>>(out);
}